// round 1
// baseline (speedup 1.0000x reference)
#include <cuda_runtime.h>
#include <math.h>

// Problem constants (from reference setup_inputs: x[16,32,65536], box filters 5 & 11)
#define ROW_LEN   65536
#define THREADS   256
#define VPT       16                    // values per thread per tile
#define TILE      (THREADS * VPT)       // 4096
#define NTILES    (ROW_LEN / TILE)      // 16
#define HALO      5
#define SMEM_N    (TILE + 2 * HALO)     // logical staging entries (4106)
#define SMEM_F    4400                  // padded capacity (4106 + 4106/16 = 4363, rounded up)

#define TREND_SCALING       0.6f
#define DETAIL_PRESERVATION 0.85f
#define SPIKE_THRESHOLD     3.5f
#define SPIKE_DAMPING       0.35f
#define EPS_STD             1e-6f

// Intermediate "current" between the two iterations. Static __device__ global
// (runtime allocation is forbidden; this is the sanctioned scratch mechanism).
__device__ float g_scratch[16u * 32u * 65536u];

__device__ __forceinline__ int reflect_idx(int g) {
    // jnp.pad mode='reflect': -1 -> 1, -2 -> 2 ; L -> L-2, L+1 -> L-3
    if (g < 0) g = -g;
    if (g >= ROW_LEN) g = 2 * ROW_LEN - 2 - g;
    return g;
}

__device__ __forceinline__ int padidx(int i) { return i + (i >> 4); }

// One sweep over the row. STATS=true: accumulate sum/sumsq of residual (no output).
// STATS=false: apply damping with threshold thr, write combined+residual to out.
template <bool STATS>
__device__ __forceinline__ void row_pass(const float* __restrict__ in,
                                         float* __restrict__ out,
                                         float thr,
                                         float* __restrict__ stage,
                                         float& s_acc, float& ss_acc)
{
    const int tid = threadIdx.x;
    const int lbase = tid * VPT;

    for (int tile = 0; tile < NTILES; tile++) {
        const int base = tile * TILE;

        // ---- coalesced staging load (reflect handled at row edges) ----
        #pragma unroll
        for (int j0 = 0; j0 < SMEM_N; j0 += THREADS) {
            int j = j0 + tid;
            if (j < SMEM_N) {
                int g = reflect_idx(base - HALO + j);
                stage[padidx(j)] = in[g];
            }
        }
        __syncthreads();

        // ---- per-thread contiguous window into registers (conflict-free) ----
        float v[VPT + 2 * HALO];
        #pragma unroll
        for (int k = 0; k < VPT + 2 * HALO; k++)
            v[k] = stage[padidx(lbase + k)];

        // sliding window sums
        float s5 = 0.f;
        #pragma unroll
        for (int k = 3; k < 8; k++) s5 += v[k];

        float s11 = 0.f;
        if (!STATS) {
            #pragma unroll
            for (int k = 0; k < 11; k++) s11 += v[k];
        }

        float outbuf[VPT];
        #pragma unroll
        for (int o = 0; o < VPT; o++) {
            if (o) {
                s5 += v[o + 7] - v[o + 2];
                if (!STATS) s11 += v[o + 10] - v[o - 1];
            }
            float cur = v[o + 5];
            float res = cur - s5 * 0.2f;          // cur - local
            if (STATS) {
                s_acc  += res;
                ss_acc += res * res;
            } else {
                float f = (fabsf(res) > thr)
                              ? (DETAIL_PRESERVATION * SPIKE_DAMPING)
                              : DETAIL_PRESERVATION;
                // combined = 0.4*local + 0.6*trend = s5*(0.4/5) + s11*(0.6/11)
                float c = fmaf(s5, (1.0f - TREND_SCALING) * 0.2f,
                               s11 * (TREND_SCALING / 11.0f));
                outbuf[o] = fmaf(res, f, c);
            }
        }

        if (!STATS) {
            // 16 contiguous floats per thread, 64B-aligned -> 4x float4 stores
            float4* op = reinterpret_cast<float4*>(out + base + lbase);
            const float4* ob = reinterpret_cast<const float4*>(outbuf);
            #pragma unroll
            for (int q = 0; q < VPT / 4; q++) op[q] = ob[q];
        }
        __syncthreads();   // stage buffer reuse
    }
}

// Block reduction of (sum, sumsq) over THREADS threads -> threshold = 3.5 * std(ddof=1)
__device__ __forceinline__ float block_threshold(float s, float ss, float* red)
{
    __syncthreads();  // protect red[] from previous use
    const unsigned mask = 0xffffffffu;
    #pragma unroll
    for (int off = 16; off; off >>= 1) {
        s  += __shfl_down_sync(mask, s,  off);
        ss += __shfl_down_sync(mask, ss, off);
    }
    const int wid = threadIdx.x >> 5, lid = threadIdx.x & 31;
    if (lid == 0) { red[wid] = s; red[8 + wid] = ss; }
    __syncthreads();
    if (threadIdx.x < 32) {
        s  = (lid < (THREADS / 32)) ? red[lid]     : 0.f;
        ss = (lid < (THREADS / 32)) ? red[8 + lid] : 0.f;
        #pragma unroll
        for (int off = 4; off; off >>= 1) {
            s  += __shfl_down_sync(mask, s,  off);
            ss += __shfl_down_sync(mask, ss, off);
        }
        if (lid == 0) {
            const float n = (float)ROW_LEN;
            float var = (ss - s * s / n) / (n - 1.0f);
            var = fmaxf(var, 0.0f);
            float sc = fmaxf(sqrtf(var), EPS_STD);
            red[16] = sc * SPIKE_THRESHOLD;
        }
    }
    __syncthreads();
    return red[16];
}

__global__ void __launch_bounds__(THREADS)
fractal_denoise_kernel(const float* __restrict__ x, float* __restrict__ out)
{
    __shared__ float stage[SMEM_F];
    __shared__ float red[17];

    const size_t row_off = (size_t)blockIdx.x * ROW_LEN;
    const float* in0 = x + row_off;
    float* scr = g_scratch + row_off;
    float* o   = out + row_off;

    float s = 0.f, ss = 0.f;

    // Iteration 1
    row_pass<true >(in0, nullptr, 0.f, stage, s, ss);
    float thr1 = block_threshold(s, ss, red);
    row_pass<false>(in0, scr, thr1, stage, s, ss);
    __syncthreads();   // scr writes visible to whole block

    // Iteration 2
    s = 0.f; ss = 0.f;
    row_pass<true >(scr, nullptr, 0.f, stage, s, ss);
    float thr2 = block_threshold(s, ss, red);
    row_pass<false>(scr, o, thr2, stage, s, ss);
}

extern "C" void kernel_launch(void* const* d_in, const int* in_sizes, int n_in,
                              void* d_out, int out_size)
{
    const float* x = (const float*)d_in[0];
    float* out = (float*)d_out;
    const int rows = in_sizes[0] / ROW_LEN;   // 16*32 = 512
    fractal_denoise_kernel<<<rows, THREADS>>>(x, out);
}

// round 2
// speedup vs baseline: 1.5297x; 1.5297x over previous
#include <cuda_runtime.h>
#include <cooperative_groups.h>
#include <math.h>

namespace cg = cooperative_groups;

#define ROW_LEN   65536
#define CSIZE     4
#define QUARTER   (ROW_LEN / CSIZE)     // 16384 elements per CTA
#define THREADS   256
#define VPT       16
#define TILE      (THREADS * VPT)       // 4096
#define NT        (QUARTER / TILE)      // 4 tiles per quarter
#define HALO      5
#define JOFF      8                     // left halo lives at j = 3..7

#define TREND_SCALING       0.6f
#define DETAIL_PRESERVATION 0.85f
#define SPIKE_THRESHOLD     3.5f
#define SPIKE_DAMPING       0.35f
#define EPS_STD             1e-6f

// padded smem index: +1 float every 16 -> thread stride 17 (conflict-free)
__device__ __forceinline__ int PX(int j) { return j + (j >> 4); }

// smem layout (floats). Max logical j = JOFF + QUARTER + 4 = 16396 -> PX = 17420.
#define N_DATA      17424
#define OFF_STASH   N_DATA              // 16 floats (2 x 8, ping-pong)
#define OFF_RED     (N_DATA + 16)       // 20 floats
#define OFF_MAIL    (N_DATA + 36)       // 4 floats
#define SMEM_FLOATS (N_DATA + 40)
#define SMEM_BYTES  (SMEM_FLOATS * 4)

// Shared inner compute for the update pass: sliding box5/box11 over v[26].
__device__ __forceinline__ void update_window(const float* v, float thr, float* ob)
{
    float s5  = v[3] + v[4] + v[5] + v[6] + v[7];
    float s11 = v[0] + v[1] + v[2] + v[3] + v[4] + v[5] +
                v[6] + v[7] + v[8] + v[9] + v[10];
    #pragma unroll
    for (int o = 0; o < VPT; o++) {
        if (o) { s5 += v[o + 7] - v[o + 2]; s11 += v[o + 10] - v[o - 1]; }
        float res = v[o + 5] - 0.2f * s5;
        float f = (fabsf(res) > thr) ? (DETAIL_PRESERVATION * SPIKE_DAMPING)
                                     : DETAIL_PRESERVATION;
        float c = fmaf(s5, (1.0f - TREND_SCALING) * 0.2f,
                       s11 * (TREND_SCALING / 11.0f));
        ob[o] = fmaf(res, f, c);
    }
}

__global__ void __launch_bounds__(THREADS, 3) __cluster_dims__(CSIZE, 1, 1)
fd_cluster_kernel(const float* __restrict__ x, float* __restrict__ out)
{
    extern __shared__ float sm[];
    float* data  = sm;
    float* stash = sm + OFF_STASH;
    float* red   = sm + OFF_RED;
    float* mail  = sm + OFF_MAIL;

    cg::cluster_group cl = cg::this_cluster();
    const int rank = (int)cl.block_rank();
    const int row  = blockIdx.x / CSIZE;
    const int tid  = threadIdx.x;
    const size_t gbase = (size_t)row * ROW_LEN + (size_t)rank * QUARTER;

    // ---- stage quarter-row into smem (coalesced float4 loads) ----
    {
        const float4* gx = reinterpret_cast<const float4*>(x + gbase);
        #pragma unroll
        for (int g = 0; g < QUARTER / (THREADS * 4); g++) {   // 16
            int q = g * (THREADS * 4) + tid * 4;
            float4 v = gx[q >> 2];
            data[PX(JOFF + q + 0)] = v.x;
            data[PX(JOFF + q + 1)] = v.y;
            data[PX(JOFF + q + 2)] = v.z;
            data[PX(JOFF + q + 3)] = v.w;
        }
    }
    __syncthreads();

    for (int iter = 0; iter < 2; iter++) {
        cl.sync();   // all CTAs' data finalized cluster-wide

        // ---- halo fill (5 left, 5 right) via DSMEM / reflect ----
        if (tid < HALO) {
            int d = tid + 1;            // 1..5
            float lv;
            if (rank == 0) {
                lv = data[PX(JOFF + d)];                    // reflect: pos -d -> d
            } else {
                const float* peer = cl.map_shared_rank(sm, rank - 1);
                lv = peer[PX(JOFF + QUARTER - d)];
            }
            data[PX(JOFF - d)] = lv;

            int k = tid;                // 0..4
            float rv;
            if (rank == CSIZE - 1) {
                rv = data[PX(JOFF + QUARTER - 2 - k)];      // reflect: L+k -> L-2-k
            } else {
                const float* peer = cl.map_shared_rank(sm, rank + 1);
                rv = peer[PX(JOFF + k)];
            }
            data[PX(JOFF + QUARTER + k)] = rv;
        }
        __syncthreads();

        // ---- stats pass: sum / sumsq of residual = cur - box5(cur) ----
        float s = 0.f, ss = 0.f;
        for (int t = 0; t < NT; t++) {
            int lbase = t * TILE + tid * VPT;
            float v[VPT + 4];
            #pragma unroll
            for (int k = 0; k < VPT + 4; k++)
                v[k] = data[PX(JOFF + lbase - 2 + k)];
            float s5 = v[0] + v[1] + v[2] + v[3] + v[4];
            #pragma unroll
            for (int o = 0; o < VPT; o++) {
                if (o) s5 += v[o + 4] - v[o - 1];
                float res = v[o + 2] - 0.2f * s5;
                s  += res;
                ss += res * res;
            }
        }

        // block reduce (8 warps), deterministic order
        const unsigned m = 0xffffffffu;
        #pragma unroll
        for (int off = 16; off; off >>= 1) {
            s  += __shfl_down_sync(m, s,  off);
            ss += __shfl_down_sync(m, ss, off);
        }
        const int wid = tid >> 5, lid = tid & 31;
        if (lid == 0) { red[wid] = s; red[8 + wid] = ss; }
        __syncthreads();
        if (tid == 0) {
            float bs = 0.f, bss = 0.f;
            #pragma unroll
            for (int w = 0; w < 8; w++) { bs += red[w]; bss += red[8 + w]; }
            mail[0] = bs;  mail[1] = bss;
        }
        cl.sync();   // mailboxes visible cluster-wide; also fences stats reads

        if (tid == 0) {
            float cs = 0.f, css = 0.f;
            #pragma unroll
            for (int r2 = 0; r2 < CSIZE; r2++) {
                const float* pm = cl.map_shared_rank(sm, r2) + OFF_MAIL;
                cs  += pm[0];
                css += pm[1];
            }
            const float n = (float)ROW_LEN;
            float var = (css - cs * cs / n) / (n - 1.0f);
            var = fmaxf(var, 0.0f);
            float sc = fmaxf(sqrtf(var), EPS_STD);
            red[16] = sc * SPIKE_THRESHOLD;
        }
        __syncthreads();
        const float thr = red[16];

        // ---- update pass ----
        if (iter == 0) {
            // in-place in smem, stash trick preserves tile-boundary originals
            for (int t = 0; t < NT; t++) {
                int lbase = t * TILE + tid * VPT;
                float v[VPT + 2 * HALO];
                if (t > 0 && tid == 0) {
                    #pragma unroll
                    for (int k = 0; k < HALO; k++)
                        v[k] = stash[(t & 1) * 8 + k];
                    #pragma unroll
                    for (int k = HALO; k < VPT + 2 * HALO; k++)
                        v[k] = data[PX(JOFF + lbase - HALO + k)];
                } else {
                    #pragma unroll
                    for (int k = 0; k < VPT + 2 * HALO; k++)
                        v[k] = data[PX(JOFF + lbase - HALO + k)];
                }
                float ob[VPT];
                update_window(v, thr, ob);
                __syncthreads();        // all reads of this tile done
                if (tid == THREADS - 1) {
                    // originals q = lbase+11..15 -> v[16..20], for next tile's left halo
                    #pragma unroll
                    for (int k = 0; k < HALO; k++)
                        stash[((t + 1) & 1) * 8 + k] = v[VPT + k];
                }
                #pragma unroll
                for (int o = 0; o < VPT; o++)
                    data[PX(JOFF + lbase + o)] = ob[o];
                __syncthreads();
            }
        } else {
            // final iteration: write straight to global (float4 stores)
            float4* go = reinterpret_cast<float4*>(out + gbase);
            for (int t = 0; t < NT; t++) {
                int lbase = t * TILE + tid * VPT;
                float v[VPT + 2 * HALO];
                #pragma unroll
                for (int k = 0; k < VPT + 2 * HALO; k++)
                    v[k] = data[PX(JOFF + lbase - HALO + k)];
                float ob[VPT];
                update_window(v, thr, ob);
                const float4* ob4 = reinterpret_cast<const float4*>(ob);
                #pragma unroll
                for (int q4 = 0; q4 < VPT / 4; q4++)
                    go[(lbase >> 2) + q4] = ob4[q4];
            }
        }
    }
}

extern "C" void kernel_launch(void* const* d_in, const int* in_sizes, int n_in,
                              void* d_out, int out_size)
{
    const float* x = (const float*)d_in[0];
    float* out = (float*)d_out;
    const int rows = in_sizes[0] / ROW_LEN;   // 512

    cudaFuncSetAttribute(fd_cluster_kernel,
                         cudaFuncAttributeMaxDynamicSharedMemorySize, SMEM_BYTES);
    fd_cluster_kernel<<<rows * CSIZE, THREADS, SMEM_BYTES>>>(x, out);
}